// round 1
// baseline (speedup 1.0000x reference)
#include <cuda_runtime.h>
#include <math.h>

#define Bb 64
#define Hh 256
#define Ll 1024
#define Nn 64
#define BHL (Bb*Hh*Ll)

// ---------------- scratch (device globals; no allocs allowed) ----------------
__device__ float g_x1[BHL];       // post-AdaLN x (residual source)
__device__ float g_z[BHL];        // z (pre-norm out) ; later reused for gated g
__device__ float g_yg[BHL];       // gelu(conv out + D*z)
__device__ float g_ss[Bb*2048];   // scale(0:1024) / shift(1024:2048) per batch
__device__ float g_semb[Bb*1024]; // silu(sin/cos emb)
__device__ float g_ktime[Hh*2048];// time-domain bidirectional kernel
__device__ float g_khr[Hh*2048];  // full complex spectrum of k (re)
__device__ float g_khi[Hh*2048];  // (im)

// ---------------- helpers ----------------
__device__ __forceinline__ float geluf(float x) {
    return 0.5f * x * (1.0f + erff(x * 0.70710678118654752440f));
}
__device__ __forceinline__ float gatef(float x) {
    return tanhf(x) * (1.0f / (1.0f + expf(-x)));
}

// ---------------- sinusoidal embedding + silu ----------------
__global__ void __launch_bounds__(256) k_semb(const int* __restrict__ t) {
    int b = blockIdx.x;
    float tf = (float)t[b];
    const float cfr = (float)(-9.210340371976184 / 511.0);   // -log(10000)/(half-1)
    #pragma unroll
    for (int r = 0; r < 4; r++) {
        int i = threadIdx.x + (r << 8);
        float v;
        if (i < 512) v = sinf(tf * expf((float)i * cfr));
        else         v = cosf(tf * expf((float)(i - 512) * cfr));
        float sg = 1.0f / (1.0f + expf(-v));
        g_semb[b * 1024 + i] = v * sg;
    }
}

// ---------------- emb @ ada_w.T + ada_b  -> scale/shift ----------------
// grid: 64 blocks over output chunks of 32; each block covers all 64 batches.
__global__ void __launch_bounds__(256) k_ada_gemm(const float* __restrict__ W,
                                                  const float* __restrict__ bias) {
    __shared__ float Ws[64][32];   // [k][o]
    __shared__ float Eb[64][64];   // [b][k]
    int o0 = blockIdx.x * 32;
    int tid = threadIdx.x;
    int o  = tid & 31;
    int bg = tid >> 5;      // 0..7, owns 8 batches
    float acc[8];
    float bo = bias[o0 + o];
    #pragma unroll
    for (int j = 0; j < 8; j++) acc[j] = bo;

    for (int kk = 0; kk < 1024; kk += 64) {
        {
            int oo = tid >> 3;       // 0..31
            int kq = tid & 7;        // 0..7
            const float* src = &W[(size_t)(o0 + oo) * 1024 + kk + kq * 8];
            float4 a = *(const float4*)(src);
            float4 c = *(const float4*)(src + 4);
            int kb = kq * 8;
            Ws[kb+0][oo] = a.x; Ws[kb+1][oo] = a.y; Ws[kb+2][oo] = a.z; Ws[kb+3][oo] = a.w;
            Ws[kb+4][oo] = c.x; Ws[kb+5][oo] = c.y; Ws[kb+6][oo] = c.z; Ws[kb+7][oo] = c.w;
        }
        #pragma unroll
        for (int r = 0; r < 16; r++) {
            int e = tid + (r << 8);
            int bq = e >> 6, k = e & 63;
            Eb[bq][k] = g_semb[bq * 1024 + kk + k];
        }
        __syncthreads();
        #pragma unroll 8
        for (int k = 0; k < 64; k++) {
            float wv = Ws[k][o];
            #pragma unroll
            for (int j = 0; j < 8; j++)
                acc[j] += Eb[bg * 8 + j][k] * wv;
        }
        __syncthreads();
    }
    #pragma unroll
    for (int j = 0; j < 8; j++)
        g_ss[(bg * 8 + j) * 2048 + o0 + o] = acc[j];
}

// ---------------- AdaLayerNorm over L: x1 = ln(x)*(1+scale)+shift ----------------
__global__ void __launch_bounds__(256) k_adaln(const float* __restrict__ x) {
    int bh = blockIdx.x;
    int b = bh >> 8;
    int tid = threadIdx.x;
    const float4* xr = (const float4*)(x + (size_t)bh * 1024);
    float4 v = xr[tid];
    float s = v.x + v.y + v.z + v.w;
    float q = v.x*v.x + v.y*v.y + v.z*v.z + v.w*v.w;
    #pragma unroll
    for (int o = 16; o; o >>= 1) {
        s += __shfl_down_sync(0xffffffffu, s, o);
        q += __shfl_down_sync(0xffffffffu, q, o);
    }
    __shared__ float as_[8], aq_[8];
    if ((tid & 31) == 0) { as_[tid >> 5] = s; aq_[tid >> 5] = q; }
    __syncthreads();
    float S = 0.f, Q = 0.f;
    #pragma unroll
    for (int i = 0; i < 8; i++) { S += as_[i]; Q += aq_[i]; }
    float m  = S * (1.0f / 1024.0f);
    float va = Q * (1.0f / 1024.0f) - m * m;
    float rs = rsqrtf(va + 1e-5f);
    const float4* sc = (const float4*)(g_ss + b * 2048);
    const float4* sh = (const float4*)(g_ss + b * 2048 + 1024);
    float4 a = sc[tid], d = sh[tid];
    float4 o4;
    o4.x = (v.x - m) * rs * (1.0f + a.x) + d.x;
    o4.y = (v.y - m) * rs * (1.0f + a.y) + d.y;
    o4.z = (v.z - m) * rs * (1.0f + a.z) + d.z;
    o4.w = (v.w - m) * rs * (1.0f + a.w) + d.w;
    ((float4*)(g_x1 + (size_t)bh * 1024))[tid] = o4;
}

// ---------------- channel LayerNorm over H ----------------
__global__ void __launch_bounds__(256) k_chanln(const float* __restrict__ nw,
                                                const float* __restrict__ nb) {
    int b = blockIdx.x;
    int l0 = blockIdx.y * 32;
    int tid = threadIdx.x;
    int lx = tid & 31, hp = tid >> 5;
    float v[32];
    float s = 0.f, q = 0.f;
    const float* base = g_x1 + ((size_t)b * Hh) * Ll + l0 + lx;
    #pragma unroll 8
    for (int k = 0; k < 32; k++) {
        float xv = base[(size_t)(hp * 32 + k) * Ll];
        v[k] = xv; s += xv; q += xv * xv;
    }
    __shared__ float ps[8][32], pq[8][32];
    __shared__ float mean_[32], rstd_[32];
    ps[hp][lx] = s; pq[hp][lx] = q;
    __syncthreads();
    if (tid < 32) {
        float S = 0.f, Q = 0.f;
        #pragma unroll
        for (int p = 0; p < 8; p++) { S += ps[p][tid]; Q += pq[p][tid]; }
        float m  = S * (1.0f / 256.0f);
        float va = Q * (1.0f / 256.0f) - m * m;
        mean_[tid] = m; rstd_[tid] = rsqrtf(va + 1e-5f);
    }
    __syncthreads();
    float m = mean_[lx], r = rstd_[lx];
    float* zb = g_z + ((size_t)b * Hh) * Ll + l0 + lx;
    #pragma unroll 8
    for (int k = 0; k < 32; k++) {
        int h = hp * 32 + k;
        zb[(size_t)h * Ll] = (v[k] - m) * r * nw[h] + nb[h];
    }
}

// ---------------- SSM kernel (time domain, bidirectional assembled) ----------------
__global__ void __launch_bounds__(256) k_ssm(const float* __restrict__ log_dt,
                                             const float* __restrict__ A_re,
                                             const float* __restrict__ A_im,
                                             const float* __restrict__ C_re,
                                             const float* __restrict__ C_im) {
    __shared__ float pre[6][64]; // dtA_re, dtA_im, c0r, c0i, c1r, c1i
    int h = blockIdx.x, tid = threadIdx.x;
    if (tid < 64) {
        int n = tid;
        float dt  = expf(log_dt[h]);
        float are = -expf(A_re[h * 64 + n]);
        float aim = A_im[h * 64 + n];
        float dre = dt * are, dim = dt * aim;
        float er = expf(dre);
        float sn, cs; sincosf(dim, &sn, &cs);
        float dAr = er * cs, dAi = er * sn;
        float numr = dAr - 1.0f, numi = dAi;
        float den = are * are + aim * aim;
        float fr = (numr * are + numi * aim) / den;
        float fi = (numi * are - numr * aim) / den;
        float c0re = C_re[h * 64 + n],             c0im = C_im[h * 64 + n];
        float c1re = C_re[Hh * 64 + h * 64 + n],   c1im = C_im[Hh * 64 + h * 64 + n];
        pre[0][n] = dre; pre[1][n] = dim;
        pre[2][n] = c0re * fr - c0im * fi; pre[3][n] = c0re * fi + c0im * fr;
        pre[4][n] = c1re * fr - c1im * fi; pre[5][n] = c1re * fi + c1im * fr;
    }
    __syncthreads();
    #pragma unroll
    for (int qq = 0; qq < 4; qq++) {
        int l = tid + (qq << 8);
        float lf = (float)l;
        float k0 = 0.f, k1 = 0.f;
        #pragma unroll 4
        for (int n = 0; n < 64; n++) {
            float pr = pre[0][n] * lf, pi = pre[1][n] * lf;
            float e = expf(pr);
            float sn, cs; sincosf(pi, &sn, &cs);
            float vr = e * cs, vi = e * sn;
            k0 += pre[2][n] * vr - pre[3][n] * vi;
            k1 += pre[4][n] * vr - pre[5][n] * vi;
        }
        g_ktime[h * 2048 + l]        = 2.0f * k0;
        g_ktime[h * 2048 + 2047 - l] = 2.0f * k1;
    }
}

// ---------------- Stockham radix-2 FFT, N=2048, 256 threads ----------------
__device__ __forceinline__ void fft2048(float*& sr, float*& si, float*& dr, float*& di,
                                        const float* twr, const float* twi) {
    int m = 1;
    #pragma unroll
    for (int st = 0; st < 11; st++) {
        #pragma unroll
        for (int qq = 0; qq < 4; qq++) {
            int idx = threadIdx.x + (qq << 8);
            int jm = idx & ~(m - 1);
            int o  = idx + jm;
            float ar = sr[idx],        ai = si[idx];
            float br = sr[idx + 1024], bi = si[idx + 1024];
            float wr = twr[jm], wi = twi[jm];
            float cr = ar - br, ci = ai - bi;
            dr[o]     = ar + br; di[o]     = ai + bi;
            dr[o + m] = cr * wr - ci * wi;
            di[o + m] = ci * wr + cr * wi;
        }
        __syncthreads();
        float* tp;
        tp = sr; sr = dr; dr = tp;
        tp = si; si = di; di = tp;
        m <<= 1;
    }
}

__device__ __forceinline__ void fill_tw(float* twr, float* twi) {
    for (int i = threadIdx.x; i < 1024; i += 256) {
        float ang = -3.14159265358979323846f * (float)i * (1.0f / 1024.0f);
        float sn, cs; sincosf(ang, &sn, &cs);
        twr[i] = cs; twi[i] = sn;
    }
}

// ---------------- FFT of kernel rows (pack 2 h per block, unpack to full spectra) ----------------
__global__ void __launch_bounds__(256) k_kfft() {
    __shared__ float bAr[2048], bAi[2048], bBr[2048], bBi[2048];
    __shared__ float twr[1024], twi[1024];
    int tid = threadIdx.x;
    int h0 = blockIdx.x * 2, h1 = h0 + 1;
    fill_tw(twr, twi);
    #pragma unroll
    for (int qq = 0; qq < 8; qq++) {
        int idx = tid + (qq << 8);
        bAr[idx] = g_ktime[h0 * 2048 + idx];
        bAi[idx] = g_ktime[h1 * 2048 + idx];
    }
    __syncthreads();
    float *sr = bAr, *si = bAi, *dr = bBr, *di = bBi;
    fft2048(sr, si, dr, di, twr, twi);
    #pragma unroll
    for (int qq = 0; qq < 8; qq++) {
        int f = tid + (qq << 8);
        int fr2 = (2048 - f) & 2047;
        float ur = sr[f],  ui = si[f];
        float vr = sr[fr2], vi = -si[fr2];
        g_khr[h0 * 2048 + f] = 0.5f * (ur + vr);
        g_khi[h0 * 2048 + f] = 0.5f * (ui + vi);
        g_khr[h1 * 2048 + f] = 0.5f * (ui - vi);
        g_khi[h1 * 2048 + f] = -0.5f * (ur - vr);
    }
}

// ---------------- main conv: 2 batch rows packed; epilogue +D*z, gelu ----------------
__global__ void __launch_bounds__(256) k_conv(const float* __restrict__ Dp) {
    __shared__ float bAr[2048], bAi[2048], bBr[2048], bBi[2048];
    __shared__ float twr[1024], twi[1024];
    int tid = threadIdx.x;
    int h  = blockIdx.x;
    int pb = blockIdx.y;
    fill_tw(twr, twi);
    const float* za = g_z + ((size_t)(2 * pb) * Hh + h) * Ll;
    const float* zb = za + (size_t)Hh * Ll;
    float ra[4], rb[4];
    #pragma unroll
    for (int qq = 0; qq < 4; qq++) {
        int idx = tid + (qq << 8);
        ra[qq] = za[idx]; rb[qq] = zb[idx];
        bAr[idx] = ra[qq]; bAi[idx] = rb[qq];
        bAr[idx + 1024] = 0.f; bAi[idx + 1024] = 0.f;
    }
    __syncthreads();
    float *sr = bAr, *si = bAi, *dr = bBr, *di = bBi;
    fft2048(sr, si, dr, di, twr, twi);
    const float* khr = g_khr + h * 2048;
    const float* khi = g_khi + h * 2048;
    const float inv = 1.0f / 2048.0f;
    #pragma unroll
    for (int qq = 0; qq < 8; qq++) {
        int f = tid + (qq << 8);
        float kr = khr[f], ki = khi[f];
        float ar = sr[f], ai = si[f];
        float pr = ar * kr - ai * ki;
        float pi = ar * ki + ai * kr;
        sr[f] = pr * inv;        // conj + scale for inverse transform
        si[f] = -pi * inv;
    }
    __syncthreads();
    fft2048(sr, si, dr, di, twr, twi);
    float Dh = Dp[h];
    float* ya = g_yg + ((size_t)(2 * pb) * Hh + h) * Ll;
    float* yb = ya + (size_t)Hh * Ll;
    #pragma unroll
    for (int qq = 0; qq < 4; qq++) {
        int idx = tid + (qq << 8);
        float v1 = sr[idx]  + Dh * ra[qq];
        float v2 = -si[idx] + Dh * rb[qq];
        ya[idx] = geluf(v1);
        yb[idx] = geluf(v2);
    }
}

// ---------------- GEMM1: x2 = out_w@yg + out_b + x1 ; g = tanh(x2)*sigmoid(x2) ----------------
__global__ void __launch_bounds__(256) k_gemm_gate(const float* __restrict__ W,
                                                   const float* __restrict__ bias) {
    __shared__ float Ws[16][68];
    __shared__ float Ys[16][68];
    int l0 = blockIdx.x * 64, o0 = blockIdx.y * 64, b = blockIdx.z;
    int tid = threadIdx.x;
    int orow = tid >> 4, lcol = tid & 15;
    float acc[16];
    #pragma unroll
    for (int i = 0; i < 16; i++) acc[i] = 0.f;

    for (int kk = 0; kk < 256; kk += 16) {
        {
            int oo = tid >> 2, kq = tid & 3;
            float4 w4 = *(const float4*)&W[(o0 + oo) * 256 + kk + kq * 4];
            Ws[kq*4+0][oo] = w4.x; Ws[kq*4+1][oo] = w4.y;
            Ws[kq*4+2][oo] = w4.z; Ws[kq*4+3][oo] = w4.w;
            int kr = tid >> 4, lq = tid & 15;
            float4 y4 = *(const float4*)&g_yg[(size_t)(b * Hh + kk + kr) * Ll + l0 + lq * 4];
            *(float4*)&Ys[kr][lq * 4] = y4;
        }
        __syncthreads();
        #pragma unroll
        for (int k = 0; k < 16; k++) {
            float4 a4 = *(const float4*)&Ws[k][orow * 4];
            float4 b4 = *(const float4*)&Ys[k][lcol * 4];
            float a_[4] = {a4.x, a4.y, a4.z, a4.w};
            float b_[4] = {b4.x, b4.y, b4.z, b4.w};
            #pragma unroll
            for (int ii = 0; ii < 4; ii++)
                #pragma unroll
                for (int jj = 0; jj < 4; jj++)
                    acc[ii * 4 + jj] += a_[ii] * b_[jj];
        }
        __syncthreads();
    }
    #pragma unroll
    for (int ii = 0; ii < 4; ii++) {
        int o = o0 + orow * 4 + ii;
        size_t base = (size_t)(b * Hh + o) * Ll + l0 + lcol * 4;
        float4 x1v = *(const float4*)&g_x1[base];
        float bo = bias[o];
        float4 r;
        r.x = gatef(acc[ii*4+0] + bo + x1v.x);
        r.y = gatef(acc[ii*4+1] + bo + x1v.y);
        r.z = gatef(acc[ii*4+2] + bo + x1v.z);
        r.w = gatef(acc[ii*4+3] + bo + x1v.w);
        *(float4*)&g_z[base] = r;   // z is dead; reuse for g
    }
}

// ---------------- GEMM2+3: out1 = lin1@g + b1 + x1 ; out2 = lin2@g + b2 ----------------
__global__ void __launch_bounds__(256) k_gemm_out(const float* __restrict__ W1,
                                                  const float* __restrict__ b1,
                                                  const float* __restrict__ W2,
                                                  const float* __restrict__ b2,
                                                  float* __restrict__ out) {
    __shared__ float W1s[16][68];
    __shared__ float W2s[16][68];
    __shared__ float Gs[16][68];
    int l0 = blockIdx.x * 64, o0 = blockIdx.y * 64, b = blockIdx.z;
    int tid = threadIdx.x;
    int orow = tid >> 4, lcol = tid & 15;
    float acc1[16], acc2[16];
    #pragma unroll
    for (int i = 0; i < 16; i++) { acc1[i] = 0.f; acc2[i] = 0.f; }

    for (int kk = 0; kk < 256; kk += 16) {
        {
            int oo = tid >> 2, kq = tid & 3;
            float4 w4 = *(const float4*)&W1[(o0 + oo) * 256 + kk + kq * 4];
            W1s[kq*4+0][oo] = w4.x; W1s[kq*4+1][oo] = w4.y;
            W1s[kq*4+2][oo] = w4.z; W1s[kq*4+3][oo] = w4.w;
            float4 v4 = *(const float4*)&W2[(o0 + oo) * 256 + kk + kq * 4];
            W2s[kq*4+0][oo] = v4.x; W2s[kq*4+1][oo] = v4.y;
            W2s[kq*4+2][oo] = v4.z; W2s[kq*4+3][oo] = v4.w;
            int kr = tid >> 4, lq = tid & 15;
            float4 g4 = *(const float4*)&g_z[(size_t)(b * Hh + kk + kr) * Ll + l0 + lq * 4];
            *(float4*)&Gs[kr][lq * 4] = g4;
        }
        __syncthreads();
        #pragma unroll
        for (int k = 0; k < 16; k++) {
            float4 a4 = *(const float4*)&W1s[k][orow * 4];
            float4 c4 = *(const float4*)&W2s[k][orow * 4];
            float4 b4 = *(const float4*)&Gs[k][lcol * 4];
            float a_[4] = {a4.x, a4.y, a4.z, a4.w};
            float c_[4] = {c4.x, c4.y, c4.z, c4.w};
            float b_[4] = {b4.x, b4.y, b4.z, b4.w};
            #pragma unroll
            for (int ii = 0; ii < 4; ii++)
                #pragma unroll
                for (int jj = 0; jj < 4; jj++) {
                    acc1[ii * 4 + jj] += a_[ii] * b_[jj];
                    acc2[ii * 4 + jj] += c_[ii] * b_[jj];
                }
        }
        __syncthreads();
    }
    #pragma unroll
    for (int ii = 0; ii < 4; ii++) {
        int o = o0 + orow * 4 + ii;
        size_t base = (size_t)(b * Hh + o) * Ll + l0 + lcol * 4;
        float4 x1v = *(const float4*)&g_x1[base];
        float bb1 = b1[o], bb2 = b2[o];
        float4 r1, r2;
        r1.x = acc1[ii*4+0] + bb1 + x1v.x;
        r1.y = acc1[ii*4+1] + bb1 + x1v.y;
        r1.z = acc1[ii*4+2] + bb1 + x1v.z;
        r1.w = acc1[ii*4+3] + bb1 + x1v.w;
        r2.x = acc2[ii*4+0] + bb2;
        r2.y = acc2[ii*4+1] + bb2;
        r2.z = acc2[ii*4+2] + bb2;
        r2.w = acc2[ii*4+3] + bb2;
        *(float4*)&out[base] = r1;
        *(float4*)&out[(size_t)BHL + base] = r2;
    }
}

// ---------------- launch ----------------
extern "C" void kernel_launch(void* const* d_in, const int* in_sizes, int n_in,
                              void* d_out, int out_size) {
    const float* x      = (const float*)d_in[0];
    const int*   t      = (const int*)  d_in[1];
    const float* ada_w  = (const float*)d_in[2];
    const float* ada_b  = (const float*)d_in[3];
    const float* norm_w = (const float*)d_in[4];
    const float* norm_b = (const float*)d_in[5];
    const float* log_dt = (const float*)d_in[6];
    const float* A_re   = (const float*)d_in[7];
    const float* A_im   = (const float*)d_in[8];
    const float* C_re   = (const float*)d_in[9];
    const float* C_im   = (const float*)d_in[10];
    const float* Dp     = (const float*)d_in[11];
    const float* out_w  = (const float*)d_in[12];
    const float* out_b  = (const float*)d_in[13];
    const float* lin1_w = (const float*)d_in[14];
    const float* lin1_b = (const float*)d_in[15];
    const float* lin2_w = (const float*)d_in[16];
    const float* lin2_b = (const float*)d_in[17];
    float* out = (float*)d_out;
    (void)in_sizes; (void)n_in; (void)out_size;

    k_semb<<<64, 256>>>(t);
    k_ssm<<<256, 256>>>(log_dt, A_re, A_im, C_re, C_im);
    k_kfft<<<128, 256>>>();
    k_ada_gemm<<<64, 256>>>(ada_w, ada_b);
    k_adaln<<<Bb * Hh, 256>>>(x);
    k_chanln<<<dim3(64, 32), 256>>>(norm_w, norm_b);
    k_conv<<<dim3(256, 32), 256>>>(Dp);
    k_gemm_gate<<<dim3(16, 4, 64), 256>>>(out_w, out_b);
    k_gemm_out<<<dim3(16, 4, 64), 256>>>(lin1_w, lin1_b, lin2_w, lin2_b, out);
}

// round 3
// speedup vs baseline: 1.0603x; 1.0603x over previous
#include <cuda_runtime.h>
#include <math.h>

#define Bb 64
#define Hh 256
#define Ll 1024
#define Nn 64
#define BHL (Bb*Hh*Ll)

// ---------------- scratch (device globals; no allocs allowed) ----------------
__device__ float g_x1[BHL];        // post-AdaLN x (residual source)
__device__ float g_z[BHL];         // z (pre-norm out) ; later reused for gated g
__device__ float g_yg[BHL];        // gelu(conv out + D*z)
__device__ float g_ss[Bb*2048];    // scale(0:1024) / shift(1024:2048) per batch
__device__ float g_semb[Bb*1024];  // silu(sin/cos emb)
__device__ float g_ktime[Hh*2048]; // time-domain bidirectional kernel
__device__ float g_khr[Hh*2048];   // full complex spectrum of k (re)
__device__ float g_khi[Hh*2048];   // (im)
__device__ float g_part[8*Bb*2048];// ada split-K partials
__device__ float2 g_tw[1024];      // FFT twiddles exp(-i*pi*k/1024)

// ---------------- helpers ----------------
__device__ __forceinline__ float geluf(float x) {
    return 0.5f * x * (1.0f + erff(x * 0.70710678118654752440f));
}
__device__ __forceinline__ float gatef(float x) {
    // tanh(x)*sigmoid(x) with one exp: t=e^-x, tanh=(1-t^2)/(1+t^2), sig=1/(1+t)
    float t  = __expf(-fmaxf(x, -30.0f));
    float t2 = t * t;
    return ((1.0f - t2) / (1.0f + t2)) * (1.0f / (1.0f + t));
}

// ---------------- twiddle table ----------------
__global__ void k_twfill() {
    int i = blockIdx.x * 256 + threadIdx.x;
    float ang = -3.14159265358979323846f * (float)i * (1.0f / 1024.0f);
    float sn, cs; sincosf(ang, &sn, &cs);
    g_tw[i] = make_float2(cs, sn);
}

// ---------------- sinusoidal embedding + silu ----------------
__global__ void __launch_bounds__(256) k_semb(const int* __restrict__ t) {
    int b = blockIdx.x;
    float tf = (float)t[b];
    const float cfr = (float)(-9.210340371976184 / 511.0);   // -log(10000)/(half-1)
    #pragma unroll
    for (int r = 0; r < 4; r++) {
        int i = threadIdx.x + (r << 8);
        float v;
        if (i < 512) v = sinf(tf * expf((float)i * cfr));
        else         v = cosf(tf * expf((float)(i - 512) * cfr));
        float sg = 1.0f / (1.0f + expf(-v));
        g_semb[b * 1024 + i] = v * sg;
    }
}

// ---------------- emb @ ada_w.T  (split-K partials) ----------------
// grid: (64 o-chunks of 32, 8 k-chunks of 128)
__global__ void __launch_bounds__(256) k_ada_gemm(const float* __restrict__ W) {
    __shared__ float Ws[64][32];   // [k][o]
    __shared__ float Eb[64][64];   // [b][k]
    int o0 = blockIdx.x * 32;
    int kc = blockIdx.y;
    int tid = threadIdx.x;
    int o  = tid & 31;
    int bg = tid >> 5;      // 0..7, owns 8 batches
    float acc[8];
    #pragma unroll
    for (int j = 0; j < 8; j++) acc[j] = 0.f;

    for (int kk = kc * 128; kk < kc * 128 + 128; kk += 64) {
        {
            int oo = tid >> 3;       // 0..31
            int kq = tid & 7;        // 0..7
            const float* src = &W[(size_t)(o0 + oo) * 1024 + kk + kq * 8];
            float4 a = *(const float4*)(src);
            float4 c = *(const float4*)(src + 4);
            int kb = kq * 8;
            Ws[kb+0][oo] = a.x; Ws[kb+1][oo] = a.y; Ws[kb+2][oo] = a.z; Ws[kb+3][oo] = a.w;
            Ws[kb+4][oo] = c.x; Ws[kb+5][oo] = c.y; Ws[kb+6][oo] = c.z; Ws[kb+7][oo] = c.w;
        }
        #pragma unroll
        for (int r = 0; r < 16; r++) {
            int e = tid + (r << 8);
            int bq = e >> 6, k = e & 63;
            Eb[bq][k] = g_semb[bq * 1024 + kk + k];
        }
        __syncthreads();
        #pragma unroll 8
        for (int k = 0; k < 64; k++) {
            float wv = Ws[k][o];
            #pragma unroll
            for (int j = 0; j < 8; j++)
                acc[j] += Eb[bg * 8 + j][k] * wv;
        }
        __syncthreads();
    }
    #pragma unroll
    for (int j = 0; j < 8; j++)
        g_part[((size_t)kc * 64 + bg * 8 + j) * 2048 + o0 + o] = acc[j];
}

__global__ void __launch_bounds__(256) k_ada_reduce(const float* __restrict__ bias) {
    int idx = blockIdx.x * 256 + threadIdx.x;   // 64*2048
    int b = idx >> 11, o = idx & 2047;
    float s = bias[o];
    #pragma unroll
    for (int kc = 0; kc < 8; kc++)
        s += g_part[((size_t)kc * 64 + b) * 2048 + o];
    g_ss[b * 2048 + o] = s;
}

// ---------------- AdaLayerNorm over L: x1 = ln(x)*(1+scale)+shift ----------------
__global__ void __launch_bounds__(256) k_adaln(const float* __restrict__ x) {
    int bh = blockIdx.x;
    int b = bh >> 8;
    int tid = threadIdx.x;
    const float4* xr = (const float4*)(x + (size_t)bh * 1024);
    float4 v = xr[tid];
    float s = v.x + v.y + v.z + v.w;
    float q = v.x*v.x + v.y*v.y + v.z*v.z + v.w*v.w;
    #pragma unroll
    for (int o = 16; o; o >>= 1) {
        s += __shfl_down_sync(0xffffffffu, s, o);
        q += __shfl_down_sync(0xffffffffu, q, o);
    }
    __shared__ float as_[8], aq_[8];
    if ((tid & 31) == 0) { as_[tid >> 5] = s; aq_[tid >> 5] = q; }
    __syncthreads();
    float S = 0.f, Q = 0.f;
    #pragma unroll
    for (int i = 0; i < 8; i++) { S += as_[i]; Q += aq_[i]; }
    float m  = S * (1.0f / 1024.0f);
    float va = Q * (1.0f / 1024.0f) - m * m;
    float rs = rsqrtf(va + 1e-5f);
    const float4* sc = (const float4*)(g_ss + b * 2048);
    const float4* sh = (const float4*)(g_ss + b * 2048 + 1024);
    float4 a = sc[tid], d = sh[tid];
    float4 o4;
    o4.x = (v.x - m) * rs * (1.0f + a.x) + d.x;
    o4.y = (v.y - m) * rs * (1.0f + a.y) + d.y;
    o4.z = (v.z - m) * rs * (1.0f + a.z) + d.z;
    o4.w = (v.w - m) * rs * (1.0f + a.w) + d.w;
    ((float4*)(g_x1 + (size_t)bh * 1024))[tid] = o4;
}

// ---------------- channel LayerNorm over H ----------------
__global__ void __launch_bounds__(256) k_chanln(const float* __restrict__ nw,
                                                const float* __restrict__ nb) {
    int b = blockIdx.x;
    int l0 = blockIdx.y * 32;
    int tid = threadIdx.x;
    int lx = tid & 31, hp = tid >> 5;
    float v[32];
    float s = 0.f, q = 0.f;
    const float* base = g_x1 + ((size_t)b * Hh) * Ll + l0 + lx;
    #pragma unroll 8
    for (int k = 0; k < 32; k++) {
        float xv = base[(size_t)(hp * 32 + k) * Ll];
        v[k] = xv; s += xv; q += xv * xv;
    }
    __shared__ float ps[8][32], pq[8][32];
    __shared__ float mean_[32], rstd_[32];
    ps[hp][lx] = s; pq[hp][lx] = q;
    __syncthreads();
    if (tid < 32) {
        float S = 0.f, Q = 0.f;
        #pragma unroll
        for (int p = 0; p < 8; p++) { S += ps[p][tid]; Q += pq[p][tid]; }
        float m  = S * (1.0f / 256.0f);
        float va = Q * (1.0f / 256.0f) - m * m;
        mean_[tid] = m; rstd_[tid] = rsqrtf(va + 1e-5f);
    }
    __syncthreads();
    float m = mean_[lx], r = rstd_[lx];
    float* zb = g_z + ((size_t)b * Hh) * Ll + l0 + lx;
    #pragma unroll 8
    for (int k = 0; k < 32; k++) {
        int h = hp * 32 + k;
        zb[(size_t)h * Ll] = (v[k] - m) * r * nw[h] + nb[h];
    }
}

// ---------------- SSM kernel (time domain, bidirectional assembled) ----------------
__global__ void __launch_bounds__(256) k_ssm(const float* __restrict__ log_dt,
                                             const float* __restrict__ A_re,
                                             const float* __restrict__ A_im,
                                             const float* __restrict__ C_re,
                                             const float* __restrict__ C_im) {
    __shared__ float pre[6][64]; // dtA_re, dtA_im, c0r, c0i, c1r, c1i
    int h = blockIdx.x, tid = threadIdx.x;
    if (tid < 64) {
        int n = tid;
        float dt  = expf(log_dt[h]);
        float are = -expf(A_re[h * 64 + n]);
        float aim = A_im[h * 64 + n];
        float dre = dt * are, dim = dt * aim;
        float er = expf(dre);
        float sn, cs; sincosf(dim, &sn, &cs);
        float dAr = er * cs, dAi = er * sn;
        float numr = dAr - 1.0f, numi = dAi;
        float den = are * are + aim * aim;
        float fr = (numr * are + numi * aim) / den;
        float fi = (numi * are - numr * aim) / den;
        float c0re = C_re[h * 64 + n],             c0im = C_im[h * 64 + n];
        float c1re = C_re[Hh * 64 + h * 64 + n],   c1im = C_im[Hh * 64 + h * 64 + n];
        pre[0][n] = dre; pre[1][n] = dim;
        pre[2][n] = c0re * fr - c0im * fi; pre[3][n] = c0re * fi + c0im * fr;
        pre[4][n] = c1re * fr - c1im * fi; pre[5][n] = c1re * fi + c1im * fr;
    }
    __syncthreads();
    #pragma unroll
    for (int qq = 0; qq < 4; qq++) {
        int l = tid + (qq << 8);
        float lf = (float)l;
        float k0 = 0.f, k1 = 0.f;
        #pragma unroll 4
        for (int n = 0; n < 64; n++) {
            float pr = pre[0][n] * lf, pi = pre[1][n] * lf;
            float e = expf(pr);
            float sn, cs; sincosf(pi, &sn, &cs);
            float vr = e * cs, vi = e * sn;
            k0 += pre[2][n] * vr - pre[3][n] * vi;
            k1 += pre[4][n] * vr - pre[5][n] * vi;
        }
        g_ktime[h * 2048 + l]        = 2.0f * k0;
        g_ktime[h * 2048 + 2047 - l] = 2.0f * k1;
    }
}

// ---------------- radix-4 Stockham FFT, N=2048, 256 threads ----------------
// 5 fused radix-4 stages (= radix-2 stages m and 2m fused in registers) + final radix-2.
__device__ __forceinline__ void fft2048_r4(float*& sr, float*& si, float*& dr, float*& di) {
    #pragma unroll
    for (int lm = 0; lm < 10; lm += 2) {   // m = 1,4,16,64,256
        const int m = 1 << lm;
        #pragma unroll
        for (int q = 0; q < 2; q++) {
            int i = threadIdx.x + (q << 8);          // 0..511
            int p = i >> lm;
            int r = i & (m - 1);
            float ar = sr[i],        ai = si[i];
            float br = sr[i + 1024], bi = si[i + 1024];
            float cr = sr[i + 512],  ci = si[i + 512];
            float er = sr[i + 1536], ei = si[i + 1536];
            float2 w = g_tw[m * p];
            // stage m, butterfly i:   u0 = a+b ; u1 = (a-b)*w
            float u0r = ar + br, u0i = ai + bi;
            float t0r = ar - br, t0i = ai - bi;
            float u1r = t0r * w.x - t0i * w.y;
            float u1i = t0i * w.x + t0r * w.y;
            // stage m, butterfly i+512: v0 = c+e ; v1 = (c-e)*w*(-i)
            float v0r = cr + er, v0i = ci + ei;
            float t1r = cr - er, t1i = ci - ei;
            float s1r = t1r * w.x - t1i * w.y;
            float s1i = t1i * w.x + t1r * w.y;
            float v1r = s1i, v1i = -s1r;             // * (-i)
            // stage 2m twiddle = w^2
            float w2r = w.x * w.x - w.y * w.y;
            float w2i = 2.0f * w.x * w.y;
            int o = 4 * m * p + r;
            dr[o]     = u0r + v0r;  di[o]     = u0i + v0i;
            dr[o + m] = u1r + v1r;  di[o + m] = u1i + v1i;
            float d2r = u0r - v0r, d2i = u0i - v0i;
            float d3r = u1r - v1r, d3i = u1i - v1i;
            dr[o + 2*m] = d2r * w2r - d2i * w2i;
            di[o + 2*m] = d2i * w2r + d2r * w2i;
            dr[o + 3*m] = d3r * w2r - d3i * w2i;
            di[o + 3*m] = d3i * w2r + d3r * w2i;
        }
        __syncthreads();
        float* tp; tp=sr;sr=dr;dr=tp; tp=si;si=di;di=tp;
    }
    // final radix-2 stage (m=1024, twiddle 1)
    #pragma unroll
    for (int q = 0; q < 4; q++) {
        int i = threadIdx.x + (q << 8);              // 0..1023
        float ar = sr[i], ai = si[i];
        float br = sr[i + 1024], bi = si[i + 1024];
        dr[i]        = ar + br;  di[i]        = ai + bi;
        dr[i + 1024] = ar - br;  di[i + 1024] = ai - bi;
    }
    __syncthreads();
    float* tp; tp=sr;sr=dr;dr=tp; tp=si;si=di;di=tp;
}

// ---------------- FFT of kernel rows (pack 2 h per block, unpack to full spectra) ----------------
__global__ void __launch_bounds__(256) k_kfft() {
    __shared__ float bAr[2048], bAi[2048], bBr[2048], bBi[2048];
    int tid = threadIdx.x;
    int h0 = blockIdx.x * 2, h1 = h0 + 1;
    #pragma unroll
    for (int qq = 0; qq < 8; qq++) {
        int idx = tid + (qq << 8);
        bAr[idx] = g_ktime[h0 * 2048 + idx];
        bAi[idx] = g_ktime[h1 * 2048 + idx];
    }
    __syncthreads();
    float *sr = bAr, *si = bAi, *dr = bBr, *di = bBi;
    fft2048_r4(sr, si, dr, di);
    #pragma unroll
    for (int qq = 0; qq < 8; qq++) {
        int f = tid + (qq << 8);
        int fr2 = (2048 - f) & 2047;
        float ur = sr[f],  ui = si[f];
        float vr = sr[fr2], vi = -si[fr2];
        g_khr[h0 * 2048 + f] = 0.5f * (ur + vr);
        g_khi[h0 * 2048 + f] = 0.5f * (ui + vi);
        g_khr[h1 * 2048 + f] = 0.5f * (ui - vi);
        g_khi[h1 * 2048 + f] = -0.5f * (ur - vr);
    }
}

// ---------------- main conv: 2 batch rows packed; epilogue +D*z, gelu ----------------
__global__ void __launch_bounds__(256) k_conv(const float* __restrict__ Dp) {
    __shared__ float bAr[2048], bAi[2048], bBr[2048], bBi[2048];
    int tid = threadIdx.x;
    int h  = blockIdx.x;
    int pb = blockIdx.y;
    const float* za = g_z + ((size_t)(2 * pb) * Hh + h) * Ll;
    const float* zb = za + (size_t)Hh * Ll;
    float ra[4], rb[4];
    #pragma unroll
    for (int qq = 0; qq < 4; qq++) {
        int idx = tid + (qq << 8);
        ra[qq] = za[idx]; rb[qq] = zb[idx];
        bAr[idx] = ra[qq]; bAi[idx] = rb[qq];
        bAr[idx + 1024] = 0.f; bAi[idx + 1024] = 0.f;
    }
    __syncthreads();
    float *sr = bAr, *si = bAi, *dr = bBr, *di = bBi;
    fft2048_r4(sr, si, dr, di);
    const float* khr = g_khr + h * 2048;
    const float* khi = g_khi + h * 2048;
    const float inv = 1.0f / 2048.0f;
    #pragma unroll
    for (int qq = 0; qq < 8; qq++) {
        int f = tid + (qq << 8);
        float kr = khr[f], ki = khi[f];
        float ar = sr[f], ai = si[f];
        float pr = ar * kr - ai * ki;
        float pi = ar * ki + ai * kr;
        sr[f] = pr * inv;        // conj + scale for inverse transform
        si[f] = -pi * inv;
    }
    __syncthreads();
    fft2048_r4(sr, si, dr, di);
    float Dh = Dp[h];
    float* ya = g_yg + ((size_t)(2 * pb) * Hh + h) * Ll;
    float* yb = ya + (size_t)Hh * Ll;
    #pragma unroll
    for (int qq = 0; qq < 4; qq++) {
        int idx = tid + (qq << 8);
        float v1 = sr[idx]  + Dh * ra[qq];
        float v2 = -si[idx] + Dh * rb[qq];
        ya[idx] = geluf(v1);
        yb[idx] = geluf(v2);
    }
}

// ---------------- big GEMM: C[o,l] = W[o,:]@X[:,l] (+bias)(+resid)(activation) ----------------
// 128x128 tile, 8x8 per thread, K=256 in chunks of 16.
// mode 0: gate(acc+b+resid) -> Yout ; mode 1: acc+b+resid ; mode 2: acc+b
__global__ void __launch_bounds__(256) k_gemm(const float* __restrict__ W,
                                              const float* __restrict__ bias,
                                              const float* __restrict__ X,
                                              const float* __restrict__ resid,
                                              float* __restrict__ Yout,
                                              int mode) {
    __shared__ float Ws[16][132];
    __shared__ float Ys[16][132];
    int l0 = blockIdx.x * 128;
    int o0 = blockIdx.y * 128;
    int b  = blockIdx.z;
    int tid = threadIdx.x;
    int ty = tid >> 4, tx = tid & 15;

    float acc[8][8];
    #pragma unroll
    for (int i = 0; i < 8; i++)
        #pragma unroll
        for (int j = 0; j < 8; j++) acc[i][j] = 0.f;

    // staging thread mapping
    int wo = tid >> 1, wk = (tid & 1) * 8;     // W: row wo, k-offset wk (8 floats)
    int yk = tid >> 4, yl = (tid & 15) * 4;    // X: row yk, cols yl and yl+64

    const float* wptr = &W[(size_t)(o0 + wo) * 256 + wk];
    const float* xptr = &X[((size_t)b * Hh + yk) * Ll + l0 + yl];

    float4 w0 = *(const float4*)(wptr);
    float4 w1 = *(const float4*)(wptr + 4);
    float4 y0 = *(const float4*)(xptr);
    float4 y1 = *(const float4*)(xptr + 64);

    #pragma unroll 1
    for (int it = 0; it < 16; it++) {
        Ws[wk+0][wo] = w0.x; Ws[wk+1][wo] = w0.y; Ws[wk+2][wo] = w0.z; Ws[wk+3][wo] = w0.w;
        Ws[wk+4][wo] = w1.x; Ws[wk+5][wo] = w1.y; Ws[wk+6][wo] = w1.z; Ws[wk+7][wo] = w1.w;
        *(float4*)&Ys[yk][yl]      = y0;
        *(float4*)&Ys[yk][yl + 64] = y1;
        __syncthreads();
        if (it < 15) {
            const float* wp = wptr + (it + 1) * 16;
            const float* xp = xptr + (size_t)(it + 1) * 16 * Ll;
            w0 = *(const float4*)(wp);
            w1 = *(const float4*)(wp + 4);
            y0 = *(const float4*)(xp);
            y1 = *(const float4*)(xp + 64);
        }
        #pragma unroll
        for (int k = 0; k < 16; k++) {
            float4 a0 = *(const float4*)&Ws[k][ty * 4];
            float4 a1 = *(const float4*)&Ws[k][ty * 4 + 64];
            float4 b0 = *(const float4*)&Ys[k][tx * 4];
            float4 b1 = *(const float4*)&Ys[k][tx * 4 + 64];
            float av[8] = {a0.x,a0.y,a0.z,a0.w,a1.x,a1.y,a1.z,a1.w};
            float bv[8] = {b0.x,b0.y,b0.z,b0.w,b1.x,b1.y,b1.z,b1.w};
            #pragma unroll
            for (int ii = 0; ii < 8; ii++)
                #pragma unroll
                for (int jj = 0; jj < 8; jj++)
                    acc[ii][jj] += av[ii] * bv[jj];
        }
        __syncthreads();
    }

    #pragma unroll
    for (int hi = 0; hi < 2; hi++)
        #pragma unroll
        for (int ii = 0; ii < 4; ii++) {
            int o = o0 + hi * 64 + ty * 4 + ii;
            float bo = bias[o];
            size_t rb = ((size_t)b * Hh + o) * Ll + l0;
            #pragma unroll
            for (int jh = 0; jh < 2; jh++) {
                int lc = jh * 64 + tx * 4;
                const float* ap = &acc[hi * 4 + ii][jh * 4];
                float4 res;
                if (mode != 2) res = *(const float4*)&resid[rb + lc];
                else           res = make_float4(0.f, 0.f, 0.f, 0.f);
                float4 r;
                r.x = ap[0] + bo + res.x;
                r.y = ap[1] + bo + res.y;
                r.z = ap[2] + bo + res.z;
                r.w = ap[3] + bo + res.w;
                if (mode == 0) {
                    r.x = gatef(r.x); r.y = gatef(r.y);
                    r.z = gatef(r.z); r.w = gatef(r.w);
                }
                *(float4*)&Yout[rb + lc] = r;
            }
        }
}

// ---------------- launch ----------------
extern "C" void kernel_launch(void* const* d_in, const int* in_sizes, int n_in,
                              void* d_out, int out_size) {
    const float* x      = (const float*)d_in[0];
    const int*   t      = (const int*)  d_in[1];
    const float* ada_w  = (const float*)d_in[2];
    const float* ada_b  = (const float*)d_in[3];
    const float* norm_w = (const float*)d_in[4];
    const float* norm_b = (const float*)d_in[5];
    const float* log_dt = (const float*)d_in[6];
    const float* A_re   = (const float*)d_in[7];
    const float* A_im   = (const float*)d_in[8];
    const float* C_re   = (const float*)d_in[9];
    const float* C_im   = (const float*)d_in[10];
    const float* Dp     = (const float*)d_in[11];
    const float* out_w  = (const float*)d_in[12];
    const float* out_b  = (const float*)d_in[13];
    const float* lin1_w = (const float*)d_in[14];
    const float* lin1_b = (const float*)d_in[15];
    const float* lin2_w = (const float*)d_in[16];
    const float* lin2_b = (const float*)d_in[17];
    float* out = (float*)d_out;
    (void)in_sizes; (void)n_in; (void)out_size;

    // device-global pointers for k_gemm arguments
    float *p_x1, *p_z, *p_yg;
    cudaGetSymbolAddress((void**)&p_x1, g_x1);
    cudaGetSymbolAddress((void**)&p_z,  g_z);
    cudaGetSymbolAddress((void**)&p_yg, g_yg);

    k_twfill<<<4, 256>>>();
    k_semb<<<64, 256>>>(t);
    k_ssm<<<256, 256>>>(log_dt, A_re, A_im, C_re, C_im);
    k_kfft<<<128, 256>>>();
    k_ada_gemm<<<dim3(64, 8), 256>>>(ada_w);
    k_ada_reduce<<<512, 256>>>(ada_b);
    k_adaln<<<Bb * Hh, 256>>>(x);
    k_chanln<<<dim3(64, 32), 256>>>(norm_w, norm_b);
    k_conv<<<dim3(256, 32), 256>>>(Dp);
    k_gemm<<<dim3(8, 2, 64), 256>>>(out_w,  out_b,  p_yg, p_x1, p_z,        0);
    k_gemm<<<dim3(8, 2, 64), 256>>>(lin1_w, lin1_b, p_z,  p_x1, out,        1);
    k_gemm<<<dim3(8, 2, 64), 256>>>(lin2_w, lin2_b, p_z,  p_x1, out + BHL,  2);
}